// round 1
// baseline (speedup 1.0000x reference)
#include <cuda_runtime.h>
#include <math_constants.h>

#define VOCAB    100000
#define RAND_DIM 100
#define WAE      50
#define CLS      4
#define VDIM     100
#define NPATH    16384
#define PLEN     50
#define HDIM     150   // RAND_DIM + WAE

// Scratch: precomputed E_wae @ W_enc  [VOCAB, WAE]  (20 MB)
__device__ float g_G[(size_t)VOCAB * WAE];
// Global max-pool accumulator [HDIM]
__device__ float g_max[HDIM];

// ---------------------------------------------------------------------------
// Float atomic max via orderable-bits trick (valid for any sign, init -inf)
// ---------------------------------------------------------------------------
__device__ __forceinline__ void atomicMaxF(float* addr, float v) {
    if (v >= 0.f) atomicMax((int*)addr, __float_as_int(v));
    else          atomicMin((unsigned int*)addr, __float_as_uint(v));
}

// ---------------------------------------------------------------------------
// Kernel 0: reset the global max accumulator
// ---------------------------------------------------------------------------
__global__ void init_gmax_kernel() {
    int i = threadIdx.x;
    if (i < HDIM) g_max[i] = -CUDART_INF_F;
}

// ---------------------------------------------------------------------------
// Kernel 1: G[v, :] = E_wae[v, :] @ W_enc      (folds the WAE linear into the
// token table so the per-path GEMM disappears and gather traffic drops 25%)
// 8 vocab rows per 256-thread block; W_enc cached in smem (20 KB).
// ---------------------------------------------------------------------------
__global__ void wae_precompute_kernel(const float* __restrict__ E_wae,
                                      const float* __restrict__ W_enc) {
    __shared__ float sW[VDIM * WAE];   // 20 KB
    __shared__ float sE[8][VDIM];      // 3.2 KB
    int tid = threadIdx.x;
    for (int i = tid; i < VDIM * WAE; i += 256) sW[i] = W_enc[i];
    int row0 = blockIdx.x * 8;
    for (int i = tid; i < 8 * VDIM; i += 256) {
        int r = i / VDIM, k = i % VDIM;
        int row = row0 + r;
        sE[r][k] = (row < VOCAB) ? E_wae[(size_t)row * VDIM + k] : 0.f;
    }
    __syncthreads();

    int w = tid >> 5, lane = tid & 31;
    int row = row0 + w;
    if (row >= VOCAB) return;
    float a0 = 0.f, a1 = 0.f;
    #pragma unroll 10
    for (int k = 0; k < VDIM; k++) {
        float e = sE[w][k];
        a0 = fmaf(e, sW[k * WAE + lane], a0);
        if (lane + 32 < WAE) a1 = fmaf(e, sW[k * WAE + lane + 32], a1);
    }
    g_G[(size_t)row * WAE + lane] = a0;
    if (lane + 32 < WAE) g_G[(size_t)row * WAE + lane + 32] = a1;
}

// ---------------------------------------------------------------------------
// Kernel 2: per-path gather-sum + activations + max-pool.
// One warp per path (8 paths / 256-thread block). Lane l owns dims
// {l, l+32, l+64, l+96, l+128}: dims <100 come from E_td, dims >=100 from G.
// Tokens are preloaded to registers and broadcast via shfl so gather loads
// have no serial dependency on the token load.
// ---------------------------------------------------------------------------
__global__ void path_gather_kernel(const int*   __restrict__ x,
                                   const float* __restrict__ E_td,
                                   const float* __restrict__ b_enc) {
    __shared__ float smax[HDIM];
    int tid = threadIdx.x;
    for (int i = tid; i < HDIM; i += 256) smax[i] = -CUDART_INF_F;
    __syncthreads();

    int warp = tid >> 5, lane = tid & 31;
    int p = blockIdx.x * 8 + warp;
    const int* xp = x + (size_t)p * PLEN;

    // Preload this path's 50 token ids into registers (lane-distributed).
    int tA = xp[lane];
    int tB = (lane < PLEN - 32) ? xp[32 + lane] : 0;

    float acc[5] = {0.f, 0.f, 0.f, 0.f, 0.f};

    #pragma unroll 2
    for (int t = 0; t < PLEN; t++) {
        int tok = (t < 32) ? __shfl_sync(0xffffffffu, tA, t)
                           : __shfl_sync(0xffffffffu, tB, t - 32);
        const float* etd = E_td + (size_t)tok * RAND_DIM;
        const float* gg  = g_G  + (size_t)tok * WAE;
        #pragma unroll
        for (int k = 0; k < 5; k++) {
            int d = lane + 32 * k;
            if (d < RAND_DIM)      acc[k] += __ldg(etd + d);
            else if (d < HDIM)     acc[k] += __ldg(gg + (d - RAND_DIM));
        }
    }

    // Activations + block-local max
    #pragma unroll
    for (int k = 0; k < 5; k++) {
        int d = lane + 32 * k;
        if (d < RAND_DIM) {
            float v = acc[k];
            v = (v > 0.f) ? v : 0.01f * v;           // leaky_relu
            atomicMaxF(&smax[d], v);
        } else if (d < HDIM) {
            float v = fmaxf(acc[k] + b_enc[d - RAND_DIM], 0.f);  // relu (leaky is identity on >=0)
            atomicMaxF(&smax[d], v);
        }
    }
    __syncthreads();

    for (int i = tid; i < HDIM; i += 256) atomicMaxF(&g_max[i], smax[i]);
}

// ---------------------------------------------------------------------------
// Kernel 3: logits -> softmax -> prob; loss = -log_softmax(prob)[argmax(y)]
// ---------------------------------------------------------------------------
__global__ void finalize_kernel(const float* __restrict__ w_out,
                                const float* __restrict__ b_out,
                                const int*   __restrict__ y,
                                float* __restrict__ out, int out_size) {
    int lane = threadIdx.x;
    float part[CLS] = {0.f, 0.f, 0.f, 0.f};
    for (int d = lane; d < HDIM; d += 32) {
        float m = g_max[d];
        #pragma unroll
        for (int c = 0; c < CLS; c++)
            part[c] = fmaf(w_out[c * HDIM + d], m, part[c]);
    }
    #pragma unroll
    for (int off = 16; off > 0; off >>= 1) {
        #pragma unroll
        for (int c = 0; c < CLS; c++)
            part[c] += __shfl_down_sync(0xffffffffu, part[c], off);
    }
    if (lane == 0) {
        float logits[CLS], prob[CLS];
        float mx = -CUDART_INF_F;
        #pragma unroll
        for (int c = 0; c < CLS; c++) {
            logits[c] = part[c] + b_out[c];
            mx = fmaxf(mx, logits[c]);
        }
        float s = 0.f;
        #pragma unroll
        for (int c = 0; c < CLS; c++) { prob[c] = expf(logits[c] - mx); s += prob[c]; }
        #pragma unroll
        for (int c = 0; c < CLS; c++) prob[c] /= s;

        // label = argmax(y) (first max, like jnp.argmax)
        int label = 0, best = y[0];
        #pragma unroll
        for (int c = 1; c < CLS; c++) if (y[c] > best) { best = y[c]; label = c; }

        // loss = -(prob[label] - logsumexp(prob))
        float mx2 = prob[0];
        #pragma unroll
        for (int c = 1; c < CLS; c++) mx2 = fmaxf(mx2, prob[c]);
        float s2 = 0.f;
        #pragma unroll
        for (int c = 0; c < CLS; c++) s2 += expf(prob[c] - mx2);
        float loss = -(prob[label] - (mx2 + logf(s2)));

        for (int c = 0; c < CLS && c < out_size; c++) out[c] = prob[c];
        if (out_size > CLS) out[CLS] = loss;
    }
}

// ---------------------------------------------------------------------------
extern "C" void kernel_launch(void* const* d_in, const int* in_sizes, int n_in,
                              void* d_out, int out_size) {
    const int*   x     = (const int*)  d_in[0];
    const int*   y     = (const int*)  d_in[1];
    const float* E_td  = (const float*)d_in[2];
    const float* E_wae = (const float*)d_in[3];
    const float* W_enc = (const float*)d_in[4];
    const float* b_enc = (const float*)d_in[5];
    const float* w_out = (const float*)d_in[6];
    const float* b_out = (const float*)d_in[7];
    float* out = (float*)d_out;

    init_gmax_kernel<<<1, 192>>>();
    wae_precompute_kernel<<<(VOCAB + 7) / 8, 256>>>(E_wae, W_enc);
    path_gather_kernel<<<NPATH / 8, 256>>>(x, E_td, b_enc);
    finalize_kernel<<<1, 32>>>(w_out, b_out, y, out, out_size);
}

// round 2
// speedup vs baseline: 1.6780x; 1.6780x over previous
#include <cuda_runtime.h>
#include <math_constants.h>

#define VOCAB    100000
#define RAND_DIM 100
#define WAE      50
#define CLS      4
#define VDIM     100
#define NPATH    16384
#define PLEN     50
#define HDIM     150     // RAND_DIM + WAE
#define PADG     52      // padded G row pitch (floats): 208 B, 16B-aligned rows, 7 sectors

typedef unsigned long long ull;

// Scratch: precomputed E_wae @ W_enc, padded pitch  [VOCAB, PADG]  (~20.8 MB)
__device__ float g_G[(size_t)VOCAB * PADG];
// Global max-pool accumulator [HDIM]
__device__ float g_max[HDIM];

// ---------------------------------------------------------------------------
// packed-f32x2 helpers (sm_103a FFMA2: 2 FMAs per instruction)
// ---------------------------------------------------------------------------
__device__ __forceinline__ ull fma2(ull a, ull b, ull c) {
    ull d;
    asm("fma.rn.f32x2 %0, %1, %2, %3;" : "=l"(d) : "l"(a), "l"(b), "l"(c));
    return d;
}
__device__ __forceinline__ ull dup2(float v) {
    ull d;
    asm("mov.b64 %0, {%1, %1};" : "=l"(d) : "f"(v));
    return d;
}
__device__ __forceinline__ void unpack2(ull v, float& lo, float& hi) {
    asm("mov.b64 {%0, %1}, %2;" : "=f"(lo), "=f"(hi) : "l"(v));
}

__device__ __forceinline__ void atomicMaxF(float* addr, float v) {
    if (v >= 0.f) atomicMax((int*)addr, __float_as_int(v));
    else          atomicMin((unsigned int*)addr, __float_as_uint(v));
}

// ---------------------------------------------------------------------------
// Kernel 1: G[v, 0:50] = E_wae[v, :] @ W_enc   (folds the WAE linear into a
// token table: kills the per-path GEMM and shrinks gather traffic).
// 64 rows / 256-thread block; 8 rows per warp as 4 row-pairs so each
// fma.rn.f32x2 does (row_even, row_odd) for one output column.
// E staged in smem transposed+rowpair-packed: one LDS.128 = operands for
// 2 row-pairs. W staged as plain floats, dup'd per k (ALU pipe, cheap).
// Also initializes g_max (block 0) so the init kernel disappears.
// ---------------------------------------------------------------------------
#define EPITCH 68   // floats per k-row of sE (64 rows + 4 pad; 4-way conflict on fill only)

__global__ void wae_precompute_kernel(const float* __restrict__ E_wae,
                                      const float* __restrict__ W_enc) {
    __shared__ float sE[VDIM * EPITCH];   // sE[k*68 + r] = E_wae[row0+r][k]   27.2 KB
    __shared__ float sW[VDIM * WAE];      // 20 KB

    int tid = threadIdx.x;
    if (blockIdx.x == 0 && tid < HDIM) g_max[tid] = -CUDART_INF_F;

    int row0 = blockIdx.x * 64;

    for (int i = tid; i < VDIM * WAE; i += 256) sW[i] = W_enc[i];
    for (int i = tid; i < 64 * VDIM; i += 256) {
        int r = i / VDIM, k = i % VDIM;            // global read coalesced over k
        int row = row0 + r;
        sE[k * EPITCH + r] = (row < VOCAB) ? E_wae[(size_t)row * VDIM + k] : 0.f;
    }
    __syncthreads();

    int w = tid >> 5, lane = tid & 31;
    bool hiCol = (lane < WAE - 32);                 // lanes 0..17 own cols 32..49

    ull acc[4][2];
    #pragma unroll
    for (int q = 0; q < 4; q++) { acc[q][0] = 0ull; acc[q][1] = 0ull; }

    #pragma unroll 4
    for (int k = 0; k < VDIM; k++) {
        // rows 8w..8w+7 at this k, packed as 4 (even,odd) f32 pairs
        const ull* ep = (const ull*)(sE + k * EPITCH + 8 * w);
        ull e0 = ep[0], e1 = ep[1], e2 = ep[2], e3 = ep[3];
        float w0 = sW[k * WAE + lane];
        float w1 = hiCol ? sW[k * WAE + 32 + lane] : 0.f;
        ull wd0 = dup2(w0), wd1 = dup2(w1);
        acc[0][0] = fma2(e0, wd0, acc[0][0]);  acc[0][1] = fma2(e0, wd1, acc[0][1]);
        acc[1][0] = fma2(e1, wd0, acc[1][0]);  acc[1][1] = fma2(e1, wd1, acc[1][1]);
        acc[2][0] = fma2(e2, wd0, acc[2][0]);  acc[2][1] = fma2(e2, wd1, acc[2][1]);
        acc[3][0] = fma2(e3, wd0, acc[3][0]);  acc[3][1] = fma2(e3, wd1, acc[3][1]);
    }

    int rbase = row0 + 8 * w;
    #pragma unroll
    for (int q = 0; q < 4; q++) {
        int r0 = rbase + 2 * q;
        if (r0 >= VOCAB) break;
        float lo, hi;
        unpack2(acc[q][0], lo, hi);
        g_G[(size_t)r0 * PADG + lane] = lo;
        g_G[(size_t)(r0 + 1) * PADG + lane] = hi;
        if (hiCol) {
            unpack2(acc[q][1], lo, hi);
            g_G[(size_t)r0 * PADG + 32 + lane] = lo;
            g_G[(size_t)(r0 + 1) * PADG + 32 + lane] = hi;
        }
    }
}

// ---------------------------------------------------------------------------
// Kernel 2: per-path gather-sum + activations + max-pool.
// One warp per path. Lane l<25 owns dims 4l..4l+3 (E_td, float4 loads);
// lane l<13 owns dims 100+4l..103+4l (G, float4 loads; pitch-52 rows are
// 16B-aligned so every row is exactly 7 sectors). 2 LDG.128 per token.
// ---------------------------------------------------------------------------
__global__ void path_gather_kernel(const int*   __restrict__ x,
                                   const float* __restrict__ E_td,
                                   const float* __restrict__ b_enc) {
    __shared__ float smax[HDIM];
    int tid = threadIdx.x;
    for (int i = tid; i < HDIM; i += 256) smax[i] = -CUDART_INF_F;
    __syncthreads();

    int warp = tid >> 5, lane = tid & 31;
    int p = blockIdx.x * 8 + warp;
    const int* xp = x + (size_t)p * PLEN;

    int tA = xp[lane];
    int tB = (lane < PLEN - 32) ? xp[32 + lane] : 0;

    const float4* E4 = (const float4*)E_td;          // 25 float4 per row
    const float4* G4 = (const float4*)g_G;           // 13 float4 per row
    bool doA = lane < 25;
    bool doB = lane < 13;

    float4 accA = make_float4(0.f, 0.f, 0.f, 0.f);
    float4 accB = make_float4(0.f, 0.f, 0.f, 0.f);

    #pragma unroll 5
    for (int t = 0; t < PLEN; t++) {
        int tok = (t < 32) ? __shfl_sync(0xffffffffu, tA, t)
                           : __shfl_sync(0xffffffffu, tB, t - 32);
        if (doA) {
            float4 v = __ldg(&E4[(size_t)tok * 25 + lane]);
            accA.x += v.x; accA.y += v.y; accA.z += v.z; accA.w += v.w;
        }
        if (doB) {
            float4 v = __ldg(&G4[(size_t)tok * 13 + lane]);
            accB.x += v.x; accB.y += v.y; accB.z += v.z; accB.w += v.w;
        }
    }

    if (doA) {   // dims 4l..4l+3, all < 100 -> leaky_relu
        float a[4] = {accA.x, accA.y, accA.z, accA.w};
        #pragma unroll
        for (int i = 0; i < 4; i++) {
            float v = a[i];
            v = (v > 0.f) ? v : 0.01f * v;
            atomicMaxF(&smax[4 * lane + i], v);
        }
    }
    if (doB) {   // dims 100+4l.. -> relu(acc + b_enc)  (leaky is identity on >=0)
        float a[4] = {accB.x, accB.y, accB.z, accB.w};
        int d0 = 4 * lane;                            // index into b_enc / WAE dims
        #pragma unroll
        for (int i = 0; i < 4; i++) {
            int d = d0 + i;
            if (d < WAE) {
                float v = fmaxf(a[i] + __ldg(&b_enc[d]), 0.f);
                atomicMaxF(&smax[RAND_DIM + d], v);
            }
        }
    }
    __syncthreads();

    for (int i = tid; i < HDIM; i += 256) atomicMaxF(&g_max[i], smax[i]);
}

// ---------------------------------------------------------------------------
// Kernel 3: logits -> softmax -> prob; loss = -log_softmax(prob)[argmax(y)]
// ---------------------------------------------------------------------------
__global__ void finalize_kernel(const float* __restrict__ w_out,
                                const float* __restrict__ b_out,
                                const int*   __restrict__ y,
                                float* __restrict__ out, int out_size) {
    int lane = threadIdx.x;
    float part[CLS] = {0.f, 0.f, 0.f, 0.f};
    for (int d = lane; d < HDIM; d += 32) {
        float m = g_max[d];
        #pragma unroll
        for (int c = 0; c < CLS; c++)
            part[c] = fmaf(w_out[c * HDIM + d], m, part[c]);
    }
    #pragma unroll
    for (int off = 16; off > 0; off >>= 1) {
        #pragma unroll
        for (int c = 0; c < CLS; c++)
            part[c] += __shfl_down_sync(0xffffffffu, part[c], off);
    }
    if (lane == 0) {
        float logits[CLS], prob[CLS];
        float mx = -CUDART_INF_F;
        #pragma unroll
        for (int c = 0; c < CLS; c++) {
            logits[c] = part[c] + b_out[c];
            mx = fmaxf(mx, logits[c]);
        }
        float s = 0.f;
        #pragma unroll
        for (int c = 0; c < CLS; c++) { prob[c] = expf(logits[c] - mx); s += prob[c]; }
        #pragma unroll
        for (int c = 0; c < CLS; c++) prob[c] /= s;

        int label = 0, best = y[0];
        #pragma unroll
        for (int c = 1; c < CLS; c++) if (y[c] > best) { best = y[c]; label = c; }

        float mx2 = prob[0];
        #pragma unroll
        for (int c = 1; c < CLS; c++) mx2 = fmaxf(mx2, prob[c]);
        float s2 = 0.f;
        #pragma unroll
        for (int c = 0; c < CLS; c++) s2 += expf(prob[c] - mx2);
        float loss = -(prob[label] - (mx2 + logf(s2)));

        for (int c = 0; c < CLS && c < out_size; c++) out[c] = prob[c];
        if (out_size > CLS) out[CLS] = loss;
    }
}

// ---------------------------------------------------------------------------
extern "C" void kernel_launch(void* const* d_in, const int* in_sizes, int n_in,
                              void* d_out, int out_size) {
    const int*   x     = (const int*)  d_in[0];
    const int*   y     = (const int*)  d_in[1];
    const float* E_td  = (const float*)d_in[2];
    const float* E_wae = (const float*)d_in[3];
    const float* W_enc = (const float*)d_in[4];
    const float* b_enc = (const float*)d_in[5];
    const float* w_out = (const float*)d_in[6];
    const float* b_out = (const float*)d_in[7];
    float* out = (float*)d_out;

    wae_precompute_kernel<<<(VOCAB + 63) / 64, 256>>>(E_wae, W_enc);
    path_gather_kernel<<<NPATH / 8, 256>>>(x, E_td, b_enc);
    finalize_kernel<<<1, 32>>>(w_out, b_out, y, out, out_size);
}